// round 2
// baseline (speedup 1.0000x reference)
#include <cuda_runtime.h>
#include <math.h>

#define Bb 64
#define Cc 8
#define Nn 2048
#define Tt 64
#define NSPLIT 8
#define GROUPS 8
#define BPG 8                              // batches per group (32 MB of x)
#define RED_BLOCKS (BPG * Cc * NSPLIT)     // 512
#define AGG_BLOCKS (BPG * 128)             // 1024
#define ALL_BLOCKS (RED_BLOCKS + AGG_BLOCKS)
#define NT4 (Nn * Tt / 4)                  // 32768 float4 per (b,c)

// atomic-free reduction partials: [b*Cc+c][split][t]  (1 MB)
__device__ float g_part[Bb * Cc * NSPLIT * Tt];

union SmemU {
    struct { float alpha[256]; float4 red[256]; } r;                  // reduce path
    struct { float W[64 * 64]; float k[8 * 64]; float m[8 * 64];
             float att[8 * 8]; } a;                                   // agg path
};

// ---------------------------------------------------------------------------
// Combined step kernel.
//  blocks [0, AGG_BLOCKS)            : aggregate group agg_g  (x hits L2)
//  blocks [AGG_BLOCKS, ALL_BLOCKS)   : reduce group red_g     (x from DRAM)
// ---------------------------------------------------------------------------
__global__ void __launch_bounds__(256)
step_kernel(const float* __restrict__ x, const float* __restrict__ Wc,
            const float* __restrict__ alpha, float* __restrict__ out,
            int agg_g, int red_g) {
    __shared__ SmemU S;
    int tid = threadIdx.x;

    if (blockIdx.x >= AGG_BLOCKS) {
        // ---------------- reduce path: k partials for group red_g ----------
        if (red_g < 0) return;
        int r     = blockIdx.x - AGG_BLOCKS;   // 0..511
        int bcl   = r >> 3;                    // 0..63  (local b*8+c)
        int split = r & 7;
        int b     = red_g * BPG + (bcl >> 3);
        int c     = bcl & 7;
        const float* xp = x + ((long)(b * Cc + c)) * Nn * Tt;

        S.r.alpha[tid] = alpha[split * 256 + tid];
        __syncthreads();

        int t4 = tid & 15, row = tid >> 4;
        int nbase = split * 256;
        float4 acc = make_float4(0.f, 0.f, 0.f, 0.f);
        #pragma unroll
        for (int i = 0; i < 16; i++) {
            int nl = row + i * 16;
            float4 v = reinterpret_cast<const float4*>(xp + (long)(nbase + nl) * Tt)[t4];
            float a = S.r.alpha[nl];
            acc.x += v.x * a; acc.y += v.y * a;
            acc.z += v.z * a; acc.w += v.w * a;
        }

        S.r.red[tid] = acc;
        __syncthreads();
        #pragma unroll
        for (int off = 8; off >= 1; off >>= 1) {
            if (row < off) {
                float4 o = S.r.red[(row + off) * 16 + t4];
                acc.x += o.x; acc.y += o.y; acc.z += o.z; acc.w += o.w;
                S.r.red[tid] = acc;
            }
            __syncthreads();
        }
        if (row == 0)
            reinterpret_cast<float4*>(
                g_part + ((long)(b * Cc + c) * NSPLIT + split) * Tt)[t4] = acc;

    } else {
        // ---------------- agg path: output for group agg_g -----------------
        if (agg_g < 0) return;
        int bl    = blockIdx.x >> 7;           // 0..7
        int chunk = blockIdx.x & 127;
        int b     = agg_g * BPG + bl;

        // --- att[b] computed redundantly per block (cheap, hidden) ---
        // Wc -> smem (16 KB, L2-hot)
        const float4* Wv = reinterpret_cast<const float4*>(Wc);
        #pragma unroll
        for (int i = 0; i < 4; i++)
            reinterpret_cast<float4*>(S.a.W)[tid + i * 256] = Wv[tid + i * 256];

        // k[c][t] = sum over 8 partials
        #pragma unroll
        for (int e = tid; e < 512; e += 256) {
            int c = e >> 6, t = e & 63;
            const float* gp = g_part + ((long)(b * Cc + c) * NSPLIT) * Tt + t;
            float s = 0.f;
            #pragma unroll
            for (int p = 0; p < NSPLIT; p++) s += gp[p * Tt];
            S.a.k[e] = s;
        }
        __syncthreads();

        // m[c][s] = sum_t k[c][t] * Wc[t][s]
        #pragma unroll
        for (int e = tid; e < 512; e += 256) {
            int c = e >> 6, s = e & 63;
            float acc = 0.f;
            #pragma unroll
            for (int t = 0; t < 64; t++) acc += S.a.k[c * 64 + t] * S.a.W[t * 64 + s];
            S.a.m[e] = acc;
        }
        __syncthreads();

        // scores[c][d] = sum_s m[c][s] * k[d][s]
        if (tid < 64) {
            int c = tid >> 3, d = tid & 7;
            float sc = 0.f;
            #pragma unroll
            for (int s = 0; s < 64; s++) sc += S.a.m[c * 64 + s] * S.a.k[d * 64 + s];
            S.a.att[tid] = sc;
        }
        __syncthreads();

        // softmax over d per row c
        if (tid < 8) {
            float mx = -1e30f;
            #pragma unroll
            for (int j = 0; j < 8; j++) mx = fmaxf(mx, S.a.att[tid * 8 + j]);
            float e[8], sum = 0.f;
            #pragma unroll
            for (int j = 0; j < 8; j++) { e[j] = __expf(S.a.att[tid * 8 + j] - mx); sum += e[j]; }
            float inv = 1.f / sum;
            #pragma unroll
            for (int j = 0; j < 8; j++) S.a.att[tid * 8 + j] = e[j] * inv;
        }
        __syncthreads();

        // --- main aggregation: 1 float4 per channel, x from L2, stream out ---
        int p = chunk * 256 + tid;
        const float4* xb = reinterpret_cast<const float4*>(x + (long)b * Cc * Nn * Tt);
        float4*       ob = reinterpret_cast<float4*>(out + (long)b * Cc * Nn * Tt);

        float4 acc[8];
        #pragma unroll
        for (int c = 0; c < 8; c++) acc[c] = make_float4(0.f, 0.f, 0.f, 0.f);

        #pragma unroll
        for (int i = 0; i < 8; i++) {
            float4 v = __ldcs(&xb[(long)i * NT4 + p]);   // last use: evict-first
            #pragma unroll
            for (int c = 0; c < 8; c++) {
                float a = S.a.att[c * 8 + i];
                acc[c].x += a * v.x; acc[c].y += a * v.y;
                acc[c].z += a * v.z; acc[c].w += a * v.w;
            }
        }
        #pragma unroll
        for (int c = 0; c < 8; c++)
            __stcs(&ob[(long)c * NT4 + p], acc[c]);      // never re-read
    }
}

// ---------------------------------------------------------------------------
extern "C" void kernel_launch(void* const* d_in, const int* in_sizes, int n_in,
                              void* d_out, int out_size) {
    const float* x     = (const float*)d_in[0];
    const float* Wc    = (const float*)d_in[1];
    const float* alpha = (const float*)d_in[2];
    float* out = (float*)d_out;

    // software pipeline: step s reduces group s while aggregating group s-1
    for (int s = 0; s <= GROUPS; s++) {
        int red_g = (s < GROUPS) ? s : -1;
        int agg_g = s - 1;
        step_kernel<<<ALL_BLOCKS, 256>>>(x, Wc, alpha, out, agg_g, red_g);
    }
}